// round 1
// baseline (speedup 1.0000x reference)
#include <cuda_runtime.h>
#include <math.h>
#include <stdint.h>

#define N_NODES 100000
#define N_EDGES 1600000
#define IN_DIM  256
#define OUT_DIM 64
#define LEAKY   0.01f

// ---------------- scratch (static device arrays; no allocation) ----------------
__device__ float g_z [N_NODES * OUT_DIM];   // 25.6 MB
__device__ float g_el[N_NODES];
__device__ float g_er[N_NODES];
__device__ float g_m [N_NODES];
__device__ float g_s [N_NODES];
__device__ float g_e [N_EDGES];             // logits, then exp(logit - max)

// ---------------- helpers ----------------
__device__ __forceinline__ void atomicMaxFloat(float* addr, float value) {
    if (value >= 0.0f) {
        atomicMax((int*)addr, __float_as_int(value));
    } else {
        atomicMin((unsigned int*)addr, __float_as_uint(value));
    }
}

// ---------------- K0: init ----------------
__global__ void k_init(float* __restrict__ out) {
    int i = blockIdx.x * blockDim.x + threadIdx.x;
    if (i < N_NODES) {
        g_m[i] = __int_as_float(0xff800000);  // -inf
        g_s[i] = 0.0f;
    }
    if (i < N_NODES * OUT_DIM) out[i] = 0.0f;
}

// ---------------- K1: z = h @ W ; el = z@a[:64] ; er = z@a[64:] ----------------
// block = 256 threads, 64 rows/block, 4x4 register tile per thread, k-chunks of 32.
__global__ void __launch_bounds__(256) k_gemm(const float* __restrict__ h,
                                              const float* __restrict__ W,
                                              const float* __restrict__ a_attn) {
    __shared__ float Ws[32][64];      // k-chunk of W
    __shared__ float hs[64][36];      // padded h tile
    __shared__ float els[64], ers[64];

    const int tid  = threadIdx.x;
    const int row0 = blockIdx.x * 64;
    const int rg = tid >> 4;          // 0..15 row group
    const int cg = tid & 15;          // 0..15 col group
    const int r0 = rg * 4;
    const int c0 = cg * 4;

    float acc[4][4];
#pragma unroll
    for (int i = 0; i < 4; i++)
#pragma unroll
        for (int j = 0; j < 4; j++) acc[i][j] = 0.0f;

    for (int k0 = 0; k0 < IN_DIM; k0 += 32) {
        // load W chunk: 32x64 floats = 512 float4, 2 per thread
        {
            const float4* Wg = (const float4*)(W + k0 * OUT_DIM);
            float4* Wsv = (float4*)&Ws[0][0];
            Wsv[tid]       = Wg[tid];
            Wsv[tid + 256] = Wg[tid + 256];
        }
        // load h tile: 64 rows x 32 k = 512 float4, 2 per thread
#pragma unroll
        for (int rep = 0; rep < 2; rep++) {
            int id = tid + rep * 256;
            int r  = id >> 3;
            int kq = id & 7;
            int grow = row0 + r;
            float4 v = make_float4(0.f, 0.f, 0.f, 0.f);
            if (grow < N_NODES)
                v = *(const float4*)(h + (size_t)grow * IN_DIM + k0 + kq * 4);
            *(float4*)&hs[r][kq * 4] = v;
        }
        __syncthreads();

#pragma unroll
        for (int kk = 0; kk < 32; kk++) {
            float4 bv = *(const float4*)&Ws[kk][c0];
            float a0 = hs[r0 + 0][kk];
            float a1 = hs[r0 + 1][kk];
            float a2 = hs[r0 + 2][kk];
            float a3 = hs[r0 + 3][kk];
            acc[0][0] += a0 * bv.x; acc[0][1] += a0 * bv.y; acc[0][2] += a0 * bv.z; acc[0][3] += a0 * bv.w;
            acc[1][0] += a1 * bv.x; acc[1][1] += a1 * bv.y; acc[1][2] += a1 * bv.z; acc[1][3] += a1 * bv.w;
            acc[2][0] += a2 * bv.x; acc[2][1] += a2 * bv.y; acc[2][2] += a2 * bv.z; acc[2][3] += a2 * bv.w;
            acc[3][0] += a3 * bv.x; acc[3][1] += a3 * bv.y; acc[3][2] += a3 * bv.z; acc[3][3] += a3 * bv.w;
        }
        __syncthreads();
    }

    // epilogue: store z tile, reduce per-row attention projections
    if (tid < 64) { els[tid] = 0.0f; ers[tid] = 0.0f; }
    __syncthreads();

    float al0 = a_attn[c0 + 0], al1 = a_attn[c0 + 1], al2 = a_attn[c0 + 2], al3 = a_attn[c0 + 3];
    float ar0 = a_attn[OUT_DIM + c0 + 0], ar1 = a_attn[OUT_DIM + c0 + 1];
    float ar2 = a_attn[OUT_DIM + c0 + 2], ar3 = a_attn[OUT_DIM + c0 + 3];

#pragma unroll
    for (int i = 0; i < 4; i++) {
        int grow = row0 + r0 + i;
        if (grow < N_NODES) {
            float4 v = make_float4(acc[i][0], acc[i][1], acc[i][2], acc[i][3]);
            *(float4*)(g_z + (size_t)grow * OUT_DIM + c0) = v;
            float pel = acc[i][0] * al0 + acc[i][1] * al1 + acc[i][2] * al2 + acc[i][3] * al3;
            float per = acc[i][0] * ar0 + acc[i][1] * ar1 + acc[i][2] * ar2 + acc[i][3] * ar3;
            atomicAdd(&els[r0 + i], pel);
            atomicAdd(&ers[r0 + i], per);
        }
    }
    __syncthreads();
    if (tid < 64) {
        int grow = row0 + tid;
        if (grow < N_NODES) {
            g_el[grow] = els[tid];
            g_er[grow] = ers[tid];
        }
    }
}

// ---------------- K2: edge logits + segment max ----------------
__global__ void k_edge_logit(const int* __restrict__ src, const int* __restrict__ dst) {
    int i = blockIdx.x * blockDim.x + threadIdx.x;
    if (i >= N_EDGES) return;
    int s = src[i];
    int d = dst[i];
    float v = g_el[s] + g_er[d];
    v = (v >= 0.0f) ? v : LEAKY * v;
    g_e[i] = v;
    atomicMaxFloat(&g_m[d], v);
}

// ---------------- K3: exp + segment sum ----------------
__global__ void k_edge_exp(const int* __restrict__ dst) {
    int i = blockIdx.x * blockDim.x + threadIdx.x;
    if (i >= N_EDGES) return;
    int d = dst[i];
    float ex = __expf(g_e[i] - g_m[d]);
    g_e[i] = ex;
    atomicAdd(&g_s[d], ex);
}

// ---------------- K4: weighted scatter-sum (8 threads / edge, v4 reductions) ----------------
__global__ void k_aggr(const int* __restrict__ src, const int* __restrict__ dst,
                       float* __restrict__ out) {
    int t = blockIdx.x * blockDim.x + threadIdx.x;
    int eid = t >> 3;
    if (eid >= N_EDGES) return;
    int sub = t & 7;

    int sN = src[eid];
    int dN = dst[eid];
    float alpha = g_e[eid] / g_s[dN];

    const float4* zp = (const float4*)(g_z + (size_t)sN * OUT_DIM);
    float*        op = out + (size_t)dN * OUT_DIM + sub * 8;

    float4 v0 = zp[sub * 2 + 0];
    float4 v1 = zp[sub * 2 + 1];
    float x0 = v0.x * alpha, y0 = v0.y * alpha, z0 = v0.z * alpha, w0 = v0.w * alpha;
    float x1 = v1.x * alpha, y1 = v1.y * alpha, z1 = v1.z * alpha, w1 = v1.w * alpha;

    asm volatile("red.global.add.v4.f32 [%0], {%1,%2,%3,%4};"
                 :: "l"(op), "f"(x0), "f"(y0), "f"(z0), "f"(w0) : "memory");
    asm volatile("red.global.add.v4.f32 [%0], {%1,%2,%3,%4};"
                 :: "l"(op + 4), "f"(x1), "f"(y1), "f"(z1), "f"(w1) : "memory");
}

// ---------------- K5: ELU in place ----------------
__global__ void k_elu(float* __restrict__ out) {
    int i = blockIdx.x * blockDim.x + threadIdx.x;
    if (i >= N_NODES * OUT_DIM) return;
    float x = out[i];
    out[i] = (x > 0.0f) ? x : expm1f(x);
}

// ---------------- launch ----------------
extern "C" void kernel_launch(void* const* d_in, const int* in_sizes, int n_in,
                              void* d_out, int out_size) {
    const float* h      = (const float*)d_in[0];
    const float* W_fc   = (const float*)d_in[1];
    const float* a_attn = (const float*)d_in[2];
    const int*   e_src  = (const int*)d_in[3];
    const int*   e_dst  = (const int*)d_in[4];
    float* out = (float*)d_out;

    k_init<<<(N_NODES * OUT_DIM + 255) / 256, 256>>>(out);
    k_gemm<<<(N_NODES + 63) / 64, 256>>>(h, W_fc, a_attn);
    k_edge_logit<<<(N_EDGES + 255) / 256, 256>>>(e_src, e_dst);
    k_edge_exp<<<(N_EDGES + 255) / 256, 256>>>(e_dst);
    k_aggr<<<(N_EDGES * 8 + 255) / 256, 256>>>(e_src, e_dst, out);
    k_elu<<<(N_NODES * OUT_DIM + 255) / 256, 256>>>(out);
}

// round 2
// speedup vs baseline: 1.3396x; 1.3396x over previous
#include <cuda_runtime.h>
#include <math.h>
#include <stdint.h>

#define N_NODES 100000
#define N_EDGES 1600000
#define IN_DIM  256
#define OUT_DIM 64
#define LEAKY   0.01f

#define SCAN_CHUNK 1024
#define NCHUNKS ((N_NODES + SCAN_CHUNK - 1) / SCAN_CHUNK)   // 98

// ---------------- scratch ----------------
__device__ float g_z  [N_NODES * OUT_DIM];   // 25.6 MB
__device__ float g_el [N_NODES];
__device__ float g_er [N_NODES];
__device__ int   g_cnt[N_NODES];
__device__ int   g_off[N_NODES + 1];
__device__ int   g_pos[N_NODES];
__device__ int   g_bsum[NCHUNKS];
__device__ int   g_csr[N_EDGES];             // src ids, dst-sorted

// ---------------- K0: zero histogram ----------------
__global__ void k_zero() {
    int i = blockIdx.x * blockDim.x + threadIdx.x;
    if (i < N_NODES) g_cnt[i] = 0;
}

// ---------------- K1: z = h @ W ; el = z@a[:64] ; er = z@a[64:] ----------------
__global__ void __launch_bounds__(256) k_gemm(const float* __restrict__ h,
                                              const float* __restrict__ W,
                                              const float* __restrict__ a_attn) {
    __shared__ float Ws[32][64];
    __shared__ float hs[64][36];
    __shared__ float els[64], ers[64];

    const int tid  = threadIdx.x;
    const int row0 = blockIdx.x * 64;
    const int rg = tid >> 4;
    const int cg = tid & 15;
    const int r0 = rg * 4;
    const int c0 = cg * 4;

    float acc[4][4];
#pragma unroll
    for (int i = 0; i < 4; i++)
#pragma unroll
        for (int j = 0; j < 4; j++) acc[i][j] = 0.0f;

    for (int k0 = 0; k0 < IN_DIM; k0 += 32) {
        {
            const float4* Wg = (const float4*)(W + k0 * OUT_DIM);
            float4* Wsv = (float4*)&Ws[0][0];
            Wsv[tid]       = Wg[tid];
            Wsv[tid + 256] = Wg[tid + 256];
        }
#pragma unroll
        for (int rep = 0; rep < 2; rep++) {
            int id = tid + rep * 256;
            int r  = id >> 3;
            int kq = id & 7;
            int grow = row0 + r;
            float4 v = make_float4(0.f, 0.f, 0.f, 0.f);
            if (grow < N_NODES)
                v = *(const float4*)(h + (size_t)grow * IN_DIM + k0 + kq * 4);
            *(float4*)&hs[r][kq * 4] = v;
        }
        __syncthreads();

#pragma unroll
        for (int kk = 0; kk < 32; kk++) {
            float4 bv = *(const float4*)&Ws[kk][c0];
            float a0 = hs[r0 + 0][kk];
            float a1 = hs[r0 + 1][kk];
            float a2 = hs[r0 + 2][kk];
            float a3 = hs[r0 + 3][kk];
            acc[0][0] += a0 * bv.x; acc[0][1] += a0 * bv.y; acc[0][2] += a0 * bv.z; acc[0][3] += a0 * bv.w;
            acc[1][0] += a1 * bv.x; acc[1][1] += a1 * bv.y; acc[1][2] += a1 * bv.z; acc[1][3] += a1 * bv.w;
            acc[2][0] += a2 * bv.x; acc[2][1] += a2 * bv.y; acc[2][2] += a2 * bv.z; acc[2][3] += a2 * bv.w;
            acc[3][0] += a3 * bv.x; acc[3][1] += a3 * bv.y; acc[3][2] += a3 * bv.z; acc[3][3] += a3 * bv.w;
        }
        __syncthreads();
    }

    if (tid < 64) { els[tid] = 0.0f; ers[tid] = 0.0f; }
    __syncthreads();

    float al0 = a_attn[c0 + 0], al1 = a_attn[c0 + 1], al2 = a_attn[c0 + 2], al3 = a_attn[c0 + 3];
    float ar0 = a_attn[OUT_DIM + c0 + 0], ar1 = a_attn[OUT_DIM + c0 + 1];
    float ar2 = a_attn[OUT_DIM + c0 + 2], ar3 = a_attn[OUT_DIM + c0 + 3];

#pragma unroll
    for (int i = 0; i < 4; i++) {
        int grow = row0 + r0 + i;
        if (grow < N_NODES) {
            float4 v = make_float4(acc[i][0], acc[i][1], acc[i][2], acc[i][3]);
            *(float4*)(g_z + (size_t)grow * OUT_DIM + c0) = v;
            float pel = acc[i][0] * al0 + acc[i][1] * al1 + acc[i][2] * al2 + acc[i][3] * al3;
            float per = acc[i][0] * ar0 + acc[i][1] * ar1 + acc[i][2] * ar2 + acc[i][3] * ar3;
            atomicAdd(&els[r0 + i], pel);
            atomicAdd(&ers[r0 + i], per);
        }
    }
    __syncthreads();
    if (tid < 64) {
        int grow = row0 + tid;
        if (grow < N_NODES) {
            g_el[grow] = els[tid];
            g_er[grow] = ers[tid];
        }
    }
}

// ---------------- K2: histogram of dst ----------------
__global__ void k_hist(const int* __restrict__ dst) {
    int i = blockIdx.x * blockDim.x + threadIdx.x;
    if (i < N_EDGES) atomicAdd(&g_cnt[dst[i]], 1);
}

// ---------------- K3a: per-chunk exclusive scan ----------------
__global__ void __launch_bounds__(SCAN_CHUNK) k_scan1() {
    __shared__ int sh[SCAN_CHUNK];
    int tid = threadIdx.x;
    int i = blockIdx.x * SCAN_CHUNK + tid;
    int x = (i < N_NODES) ? g_cnt[i] : 0;
    sh[tid] = x;
    __syncthreads();
#pragma unroll
    for (int off = 1; off < SCAN_CHUNK; off <<= 1) {
        int v = (tid >= off) ? sh[tid - off] : 0;
        __syncthreads();
        sh[tid] += v;
        __syncthreads();
    }
    if (i <= N_NODES) g_off[i] = sh[tid] - x;   // exclusive within chunk
    if (tid == SCAN_CHUNK - 1) g_bsum[blockIdx.x] = sh[tid];
}

// ---------------- K3b: scan chunk totals (single block) ----------------
__global__ void k_scan2() {
    __shared__ int sh[128];
    int tid = threadIdx.x;
    int x = (tid < NCHUNKS) ? g_bsum[tid] : 0;
    sh[tid] = x;
    __syncthreads();
#pragma unroll
    for (int off = 1; off < 128; off <<= 1) {
        int v = (tid >= off) ? sh[tid - off] : 0;
        __syncthreads();
        sh[tid] += v;
        __syncthreads();
    }
    if (tid < NCHUNKS) g_bsum[tid] = sh[tid] - x;  // exclusive
    if (tid == 0) g_off[N_NODES] = N_EDGES;
}

// ---------------- K3c: add chunk offsets, init scatter cursors ----------------
__global__ void k_scan3() {
    int i = blockIdx.x * blockDim.x + threadIdx.x;
    if (i < N_NODES) {
        int v = g_off[i] + g_bsum[i / SCAN_CHUNK];
        g_off[i] = v;
        g_pos[i] = v;
    }
}

// ---------------- K4: scatter edges into CSR ----------------
__global__ void k_scatter(const int* __restrict__ src, const int* __restrict__ dst) {
    int i = blockIdx.x * blockDim.x + threadIdx.x;
    if (i >= N_EDGES) return;
    int d = dst[i];
    int p = atomicAdd(&g_pos[d], 1);
    g_csr[p] = src[i];
}

// ---------------- K5: fused softmax + weighted gather + ELU (warp per dst) ----------------
__global__ void __launch_bounds__(256) k_aggr(float* __restrict__ out) {
    int gw   = (blockIdx.x * blockDim.x + threadIdx.x) >> 5;
    int lane = threadIdx.x & 31;
    if (gw >= N_NODES) return;
    const int d   = gw;
    const int beg = g_off[d];
    const int end = g_off[d + 1];
    const float erd = g_er[d];

    // ---- pass A: online softmax (max + sum) ----
    const float NEG_INF = __int_as_float(0xff800000);
    float m = NEG_INF, s = 0.0f;
    for (int j = beg + lane; j < end; j += 32) {
        int sn = g_csr[j];
        float e = g_el[sn] + erd;
        e = (e >= 0.0f) ? e : LEAKY * e;
        float mn = fmaxf(m, e);
        s = s * __expf(m - mn) + __expf(e - mn);   // m=-inf => exp(-inf)=0, e finite
        m = mn;
    }
    // warp merge with rescale
#pragma unroll
    for (int o = 16; o; o >>= 1) {
        float mo = __shfl_xor_sync(0xffffffffu, m, o);
        float so = __shfl_xor_sync(0xffffffffu, s, o);
        float mn = fmaxf(m, mo);
        float sa = (m  == NEG_INF) ? 0.0f : s  * __expf(m  - mn);
        float sb = (mo == NEG_INF) ? 0.0f : so * __expf(mo - mn);
        s = sa + sb;
        m = mn;
    }
    float rs = (s > 0.0f) ? (1.0f / s) : 0.0f;

    // ---- pass B: weighted gather of z ----
    float acc0 = 0.0f, acc1 = 0.0f;
    for (int j0 = beg; j0 < end; j0 += 32) {
        int j = j0 + lane;
        int sn = 0;
        float ax = 0.0f;
        if (j < end) {
            sn = g_csr[j];
            float e = g_el[sn] + erd;
            e = (e >= 0.0f) ? e : LEAKY * e;
            ax = __expf(e - m) * rs;
        }
        int cnt = min(32, end - j0);
#pragma unroll 4
        for (int t = 0; t < cnt; t++) {
            int   sj = __shfl_sync(0xffffffffu, sn, t);
            float aj = __shfl_sync(0xffffffffu, ax, t);
            const float* zp = g_z + (size_t)sj * OUT_DIM;
            acc0 += aj * zp[lane];
            acc1 += aj * zp[32 + lane];
        }
    }

    // ---- fused ELU + store ----
    float o0 = (acc0 > 0.0f) ? acc0 : expm1f(acc0);
    float o1 = (acc1 > 0.0f) ? acc1 : expm1f(acc1);
    out[(size_t)d * OUT_DIM + lane]      = o0;
    out[(size_t)d * OUT_DIM + 32 + lane] = o1;
}

// ---------------- launch ----------------
extern "C" void kernel_launch(void* const* d_in, const int* in_sizes, int n_in,
                              void* d_out, int out_size) {
    const float* h      = (const float*)d_in[0];
    const float* W_fc   = (const float*)d_in[1];
    const float* a_attn = (const float*)d_in[2];
    const int*   e_src  = (const int*)d_in[3];
    const int*   e_dst  = (const int*)d_in[4];
    float* out = (float*)d_out;

    k_zero<<<(N_NODES + 255) / 256, 256>>>();
    k_gemm<<<(N_NODES + 63) / 64, 256>>>(h, W_fc, a_attn);
    k_hist<<<(N_EDGES + 255) / 256, 256>>>(e_dst);
    k_scan1<<<NCHUNKS, SCAN_CHUNK>>>();
    k_scan2<<<1, 128>>>();
    k_scan3<<<(N_NODES + 255) / 256, 256>>>();
    k_scatter<<<(N_EDGES + 255) / 256, 256>>>(e_src, e_dst);
    k_aggr<<<(N_NODES * 32 + 255) / 256, 256>>>(out);
}

// round 3
// speedup vs baseline: 1.8755x; 1.4000x over previous
#include <cuda_runtime.h>
#include <math.h>
#include <stdint.h>

#define N_NODES 100000
#define N_EDGES 1600000
#define IN_DIM  256
#define OUT_DIM 64
#define LEAKY   0.01f

#define SCAN_CHUNK 1024
#define NCHUNKS ((N_NODES + SCAN_CHUNK - 1) / SCAN_CHUNK)   // 98

// ---------------- scratch ----------------
__device__ float g_z  [N_NODES * OUT_DIM];   // 25.6 MB
__device__ float g_el [N_NODES];
__device__ float g_er [N_NODES];
__device__ int   g_cnt[N_NODES];
__device__ int   g_off[N_NODES + 1];
__device__ int   g_pos[N_NODES];
__device__ int   g_bsum[NCHUNKS];
__device__ int   g_csr[N_EDGES];             // src ids, dst-sorted

// ---------------- helpers ----------------
__device__ __forceinline__ float cvt_tf32(float x) {
    uint32_t o;
    asm("cvt.rna.tf32.f32 %0, %1;" : "=r"(o) : "f"(x));
    return __uint_as_float(o);
}

__device__ __forceinline__ void mma_tf32(float& d0, float& d1, float& d2, float& d3,
                                         uint32_t a0, uint32_t a1, uint32_t a2, uint32_t a3,
                                         uint32_t b0, uint32_t b1) {
    asm volatile("mma.sync.aligned.m16n8k8.row.col.f32.tf32.tf32.f32 "
                 "{%0,%1,%2,%3}, {%4,%5,%6,%7}, {%8,%9}, {%0,%1,%2,%3};"
                 : "+f"(d0), "+f"(d1), "+f"(d2), "+f"(d3)
                 : "r"(a0), "r"(a1), "r"(a2), "r"(a3), "r"(b0), "r"(b1));
}

// ---------------- K0: zero histogram ----------------
__global__ void k_zero() {
    int i = blockIdx.x * blockDim.x + threadIdx.x;
    if (i < N_NODES) g_cnt[i] = 0;
}

// ---------------- K1: tensor-core GEMM: z = h@W ; el/er fused epilogue ----------------
// block = 256 threads (8 warps). tile = 128 rows x 64 cols. k-chunks of 32.
// warp w owns rows [16w, 16w+16) of the tile, all 64 cols: 8 n-tiles of m16n8k8.
__global__ void __launch_bounds__(256) k_gemm(const float* __restrict__ h,
                                              const float* __restrict__ W,
                                              const float* __restrict__ a_attn) {
    __shared__ float As[128][36];   // pad 36: conflict-free A frag loads
    __shared__ float Bs[32][72];    // pad 72: conflict-free B frag loads

    const int tid  = threadIdx.x;
    const int warp = tid >> 5;
    const int lane = tid & 31;
    const int m0   = blockIdx.x * 128;
    const int wrow = warp * 16;
    const int r = lane >> 2;        // 0..7
    const int c = lane & 3;         // 0..3

    float d[8][4];
#pragma unroll
    for (int j = 0; j < 8; j++)
#pragma unroll
        for (int q = 0; q < 4; q++) d[j][q] = 0.0f;

    for (int k0 = 0; k0 < IN_DIM; k0 += 32) {
        // stage A tile: 128 rows x 32 k  (4 float4 per thread)
#pragma unroll
        for (int i = 0; i < 4; i++) {
            int id  = tid + i * 256;        // 0..1023
            int row = id >> 3;
            int kq  = id & 7;
            float4 v = make_float4(0.f, 0.f, 0.f, 0.f);
            if (m0 + row < N_NODES)
                v = *(const float4*)(h + (size_t)(m0 + row) * IN_DIM + k0 + kq * 4);
            v.x = cvt_tf32(v.x); v.y = cvt_tf32(v.y);
            v.z = cvt_tf32(v.z); v.w = cvt_tf32(v.w);
            *(float4*)&As[row][kq * 4] = v;
        }
        // stage B tile: 32 k x 64 n  (2 float4 per thread)
#pragma unroll
        for (int i = 0; i < 2; i++) {
            int id = tid + i * 256;         // 0..511
            int kk = id >> 4;
            int nq = id & 15;
            float4 v = *(const float4*)(W + (size_t)(k0 + kk) * OUT_DIM + nq * 4);
            v.x = cvt_tf32(v.x); v.y = cvt_tf32(v.y);
            v.z = cvt_tf32(v.z); v.w = cvt_tf32(v.w);
            *(float4*)&Bs[kk][nq * 4] = v;
        }
        __syncthreads();

#pragma unroll
        for (int ks = 0; ks < 32; ks += 8) {
            uint32_t a0 = __float_as_uint(As[wrow + r    ][ks + c    ]);
            uint32_t a1 = __float_as_uint(As[wrow + r + 8][ks + c    ]);
            uint32_t a2 = __float_as_uint(As[wrow + r    ][ks + c + 4]);
            uint32_t a3 = __float_as_uint(As[wrow + r + 8][ks + c + 4]);
#pragma unroll
            for (int j = 0; j < 8; j++) {
                uint32_t b0 = __float_as_uint(Bs[ks + c    ][8 * j + r]);
                uint32_t b1 = __float_as_uint(Bs[ks + c + 4][8 * j + r]);
                mma_tf32(d[j][0], d[j][1], d[j][2], d[j][3], a0, a1, a2, a3, b0, b1);
            }
        }
        __syncthreads();
    }

    // ---- epilogue: store z, compute el/er (no atomics: rows unique per warp) ----
    const int row_lo = m0 + wrow + r;
    const int row_hi = row_lo + 8;

    float pl0 = 0.f, pl1 = 0.f, pr0 = 0.f, pr1 = 0.f;
#pragma unroll
    for (int j = 0; j < 8; j++) {
        int n = 8 * j + 2 * c;
        float al0 = a_attn[n], al1 = a_attn[n + 1];
        float ar0 = a_attn[OUT_DIM + n], ar1 = a_attn[OUT_DIM + n + 1];
        pl0 += d[j][0] * al0 + d[j][1] * al1;
        pr0 += d[j][0] * ar0 + d[j][1] * ar1;
        pl1 += d[j][2] * al0 + d[j][3] * al1;
        pr1 += d[j][2] * ar0 + d[j][3] * ar1;
        if (row_lo < N_NODES)
            *(float2*)(g_z + (size_t)row_lo * OUT_DIM + n) = make_float2(d[j][0], d[j][1]);
        if (row_hi < N_NODES)
            *(float2*)(g_z + (size_t)row_hi * OUT_DIM + n) = make_float2(d[j][2], d[j][3]);
    }
    // reduce across the quad (lane&3)
#pragma unroll
    for (int o = 1; o <= 2; o <<= 1) {
        pl0 += __shfl_xor_sync(0xffffffffu, pl0, o);
        pl1 += __shfl_xor_sync(0xffffffffu, pl1, o);
        pr0 += __shfl_xor_sync(0xffffffffu, pr0, o);
        pr1 += __shfl_xor_sync(0xffffffffu, pr1, o);
    }
    if (c == 0) {
        if (row_lo < N_NODES) { g_el[row_lo] = pl0; g_er[row_lo] = pr0; }
        if (row_hi < N_NODES) { g_el[row_hi] = pl1; g_er[row_hi] = pr1; }
    }
}

// ---------------- K2: histogram of dst ----------------
__global__ void k_hist(const int* __restrict__ dst) {
    int i = blockIdx.x * blockDim.x + threadIdx.x;
    if (i < N_EDGES) atomicAdd(&g_cnt[dst[i]], 1);
}

// ---------------- K3a: per-chunk exclusive scan ----------------
__global__ void __launch_bounds__(SCAN_CHUNK) k_scan1() {
    __shared__ int sh[SCAN_CHUNK];
    int tid = threadIdx.x;
    int i = blockIdx.x * SCAN_CHUNK + tid;
    int x = (i < N_NODES) ? g_cnt[i] : 0;
    sh[tid] = x;
    __syncthreads();
#pragma unroll
    for (int off = 1; off < SCAN_CHUNK; off <<= 1) {
        int v = (tid >= off) ? sh[tid - off] : 0;
        __syncthreads();
        sh[tid] += v;
        __syncthreads();
    }
    if (i <= N_NODES) g_off[i] = sh[tid] - x;   // exclusive within chunk
    if (tid == SCAN_CHUNK - 1) g_bsum[blockIdx.x] = sh[tid];
}

// ---------------- K3b: scan chunk totals (single block) ----------------
__global__ void k_scan2() {
    __shared__ int sh[128];
    int tid = threadIdx.x;
    int x = (tid < NCHUNKS) ? g_bsum[tid] : 0;
    sh[tid] = x;
    __syncthreads();
#pragma unroll
    for (int off = 1; off < 128; off <<= 1) {
        int v = (tid >= off) ? sh[tid - off] : 0;
        __syncthreads();
        sh[tid] += v;
        __syncthreads();
    }
    if (tid < NCHUNKS) g_bsum[tid] = sh[tid] - x;  // exclusive
    if (tid == 0) g_off[N_NODES] = N_EDGES;
}

// ---------------- K3c: add chunk offsets, init scatter cursors ----------------
__global__ void k_scan3() {
    int i = blockIdx.x * blockDim.x + threadIdx.x;
    if (i < N_NODES) {
        int v = g_off[i] + g_bsum[i / SCAN_CHUNK];
        g_off[i] = v;
        g_pos[i] = v;
    }
}

// ---------------- K4: scatter edges into CSR ----------------
__global__ void k_scatter(const int* __restrict__ src, const int* __restrict__ dst) {
    int i = blockIdx.x * blockDim.x + threadIdx.x;
    if (i >= N_EDGES) return;
    int d = dst[i];
    int p = atomicAdd(&g_pos[d], 1);
    g_csr[p] = src[i];
}

// ---------------- K5: fused softmax + weighted gather + ELU (warp per dst) ----------------
__global__ void __launch_bounds__(256) k_aggr(float* __restrict__ out) {
    int gw   = (blockIdx.x * blockDim.x + threadIdx.x) >> 5;
    int lane = threadIdx.x & 31;
    if (gw >= N_NODES) return;
    const int d   = gw;
    const int beg = g_off[d];
    const int end = g_off[d + 1];
    const float erd = g_er[d];

    // ---- pass A: online softmax (max + sum) ----
    const float NEG_INF = __int_as_float(0xff800000);
    float m = NEG_INF, s = 0.0f;
    for (int j = beg + lane; j < end; j += 32) {
        int sn = g_csr[j];
        float e = g_el[sn] + erd;
        e = (e >= 0.0f) ? e : LEAKY * e;
        float mn = fmaxf(m, e);
        s = s * __expf(m - mn) + __expf(e - mn);
        m = mn;
    }
#pragma unroll
    for (int o = 16; o; o >>= 1) {
        float mo = __shfl_xor_sync(0xffffffffu, m, o);
        float so = __shfl_xor_sync(0xffffffffu, s, o);
        float mn = fmaxf(m, mo);
        float sa = (m  == NEG_INF) ? 0.0f : s  * __expf(m  - mn);
        float sb = (mo == NEG_INF) ? 0.0f : so * __expf(mo - mn);
        s = sa + sb;
        m = mn;
    }
    float rs = (s > 0.0f) ? (1.0f / s) : 0.0f;

    // ---- pass B: weighted gather of z ----
    float acc0 = 0.0f, acc1 = 0.0f;
    for (int j0 = beg; j0 < end; j0 += 32) {
        int j = j0 + lane;
        int sn = 0;
        float ax = 0.0f;
        if (j < end) {
            sn = g_csr[j];
            float e = g_el[sn] + erd;
            e = (e >= 0.0f) ? e : LEAKY * e;
            ax = __expf(e - m) * rs;
        }
        int cnt = min(32, end - j0);
#pragma unroll 4
        for (int t = 0; t < cnt; t++) {
            int   sj = __shfl_sync(0xffffffffu, sn, t);
            float aj = __shfl_sync(0xffffffffu, ax, t);
            const float* zp = g_z + (size_t)sj * OUT_DIM;
            acc0 += aj * zp[lane];
            acc1 += aj * zp[32 + lane];
        }
    }

    float o0 = (acc0 > 0.0f) ? acc0 : expm1f(acc0);
    float o1 = (acc1 > 0.0f) ? acc1 : expm1f(acc1);
    out[(size_t)d * OUT_DIM + lane]      = o0;
    out[(size_t)d * OUT_DIM + 32 + lane] = o1;
}

// ---------------- launch ----------------
extern "C" void kernel_launch(void* const* d_in, const int* in_sizes, int n_in,
                              void* d_out, int out_size) {
    const float* h      = (const float*)d_in[0];
    const float* W_fc   = (const float*)d_in[1];
    const float* a_attn = (const float*)d_in[2];
    const int*   e_src  = (const int*)d_in[3];
    const int*   e_dst  = (const int*)d_in[4];
    float* out = (float*)d_out;

    k_zero<<<(N_NODES + 255) / 256, 256>>>();
    k_gemm<<<(N_NODES + 127) / 128, 256>>>(h, W_fc, a_attn);
    k_hist<<<(N_EDGES + 255) / 256, 256>>>(e_dst);
    k_scan1<<<NCHUNKS, SCAN_CHUNK>>>();
    k_scan2<<<1, 128>>>();
    k_scan3<<<(N_NODES + 255) / 256, 256>>>();
    k_scatter<<<(N_EDGES + 255) / 256, 256>>>(e_src, e_dst);
    k_aggr<<<(N_NODES * 32 + 255) / 256, 256>>>(out);
}

// round 4
// speedup vs baseline: 2.0078x; 1.0705x over previous
#include <cuda_runtime.h>
#include <math.h>
#include <stdint.h>

#define N_NODES 100000
#define N_EDGES 1600000
#define IN_DIM  256
#define OUT_DIM 64
#define LEAKY   0.01f

#define SCAN_CHUNK 1024
#define NCHUNKS ((N_NODES + SCAN_CHUNK - 1) / SCAN_CHUNK)   // 98

// ---------------- scratch ----------------
__device__ float g_z  [N_NODES * OUT_DIM];   // 25.6 MB (L2-resident)
__device__ float g_el [N_NODES];
__device__ float g_er [N_NODES];
__device__ int   g_cnt[N_NODES];
__device__ int   g_off[N_NODES + 1];
__device__ int   g_pos[N_NODES];
__device__ int   g_bsum[NCHUNKS];
__device__ int   g_csr[N_EDGES];             // src ids, dst-sorted

// ---------------- helpers ----------------
__device__ __forceinline__ float cvt_tf32(float x) {
    uint32_t o;
    asm("cvt.rna.tf32.f32 %0, %1;" : "=r"(o) : "f"(x));
    return __uint_as_float(o);
}

__device__ __forceinline__ float4 cvt_tf32_v4(float4 v) {
    v.x = cvt_tf32(v.x); v.y = cvt_tf32(v.y);
    v.z = cvt_tf32(v.z); v.w = cvt_tf32(v.w);
    return v;
}

__device__ __forceinline__ void mma_tf32(float& d0, float& d1, float& d2, float& d3,
                                         uint32_t a0, uint32_t a1, uint32_t a2, uint32_t a3,
                                         uint32_t b0, uint32_t b1) {
    asm volatile("mma.sync.aligned.m16n8k8.row.col.f32.tf32.tf32.f32 "
                 "{%0,%1,%2,%3}, {%4,%5,%6,%7}, {%8,%9}, {%0,%1,%2,%3};"
                 : "+f"(d0), "+f"(d1), "+f"(d2), "+f"(d3)
                 : "r"(a0), "r"(a1), "r"(a2), "r"(a3), "r"(b0), "r"(b1));
}

// ---------------- K0: zero histogram ----------------
__global__ void k_zero() {
    int i = blockIdx.x * blockDim.x + threadIdx.x;
    if (i < N_NODES) g_cnt[i] = 0;
}

// ---------------- K1: tensor-core GEMM with register-staged pipeline ----------------
// block = 256 threads (8 warps). tile = 128 rows x 64 cols. k-chunks of 32, 2-stage
// pipeline: chunk k+1 prefetched into registers while chunk k computes from smem.
__global__ void __launch_bounds__(256) k_gemm(const float* __restrict__ h,
                                              const float* __restrict__ W,
                                              const float* __restrict__ a_attn) {
    __shared__ float As[128][36];   // pad 36: conflict-free A frag loads
    __shared__ float Bs[32][72];    // pad 72: conflict-free B frag loads

    const int tid  = threadIdx.x;
    const int warp = tid >> 5;
    const int lane = tid & 31;
    const int m0   = blockIdx.x * 128;
    const int wrow = warp * 16;
    const int r = lane >> 2;        // 0..7
    const int c = lane & 3;         // 0..3

    // staging-index precompute
    int arow[4], akq[4];
#pragma unroll
    for (int i = 0; i < 4; i++) {
        int id = tid + i * 256;
        arow[i] = id >> 3;
        akq[i]  = id & 7;
    }
    int bkk[2], bnq[2];
#pragma unroll
    for (int i = 0; i < 2; i++) {
        int id = tid + i * 256;
        bkk[i] = id >> 4;
        bnq[i] = id & 15;
    }

    float d[8][4];
#pragma unroll
    for (int j = 0; j < 8; j++)
#pragma unroll
        for (int q = 0; q < 4; q++) d[j][q] = 0.0f;

    float4 ra[4], rb[2];

    // prologue: load chunk 0
#pragma unroll
    for (int i = 0; i < 4; i++) {
        float4 v = make_float4(0.f, 0.f, 0.f, 0.f);
        if (m0 + arow[i] < N_NODES)
            v = *(const float4*)(h + (size_t)(m0 + arow[i]) * IN_DIM + akq[i] * 4);
        ra[i] = cvt_tf32_v4(v);
    }
#pragma unroll
    for (int i = 0; i < 2; i++)
        rb[i] = cvt_tf32_v4(*(const float4*)(W + (size_t)bkk[i] * OUT_DIM + bnq[i] * 4));

    for (int k0 = 0; k0 < IN_DIM; k0 += 32) {
        // commit staged registers to smem
#pragma unroll
        for (int i = 0; i < 4; i++)
            *(float4*)&As[arow[i]][akq[i] * 4] = ra[i];
#pragma unroll
        for (int i = 0; i < 2; i++)
            *(float4*)&Bs[bkk[i]][bnq[i] * 4] = rb[i];
        __syncthreads();

        // prefetch next chunk (overlaps with mma below)
        int kn = k0 + 32;
        if (kn < IN_DIM) {
#pragma unroll
            for (int i = 0; i < 4; i++) {
                float4 v = make_float4(0.f, 0.f, 0.f, 0.f);
                if (m0 + arow[i] < N_NODES)
                    v = *(const float4*)(h + (size_t)(m0 + arow[i]) * IN_DIM + kn + akq[i] * 4);
                ra[i] = cvt_tf32_v4(v);
            }
#pragma unroll
            for (int i = 0; i < 2; i++)
                rb[i] = cvt_tf32_v4(*(const float4*)(W + (size_t)(kn + bkk[i]) * OUT_DIM + bnq[i] * 4));
        }

#pragma unroll
        for (int ks = 0; ks < 32; ks += 8) {
            uint32_t a0 = __float_as_uint(As[wrow + r    ][ks + c    ]);
            uint32_t a1 = __float_as_uint(As[wrow + r + 8][ks + c    ]);
            uint32_t a2 = __float_as_uint(As[wrow + r    ][ks + c + 4]);
            uint32_t a3 = __float_as_uint(As[wrow + r + 8][ks + c + 4]);
#pragma unroll
            for (int j = 0; j < 8; j++) {
                uint32_t b0 = __float_as_uint(Bs[ks + c    ][8 * j + r]);
                uint32_t b1 = __float_as_uint(Bs[ks + c + 4][8 * j + r]);
                mma_tf32(d[j][0], d[j][1], d[j][2], d[j][3], a0, a1, a2, a3, b0, b1);
            }
        }
        __syncthreads();
    }

    // ---- epilogue: store z, compute el/er (rows unique per warp, no atomics) ----
    const int row_lo = m0 + wrow + r;
    const int row_hi = row_lo + 8;

    float pl0 = 0.f, pl1 = 0.f, pr0 = 0.f, pr1 = 0.f;
#pragma unroll
    for (int j = 0; j < 8; j++) {
        int n = 8 * j + 2 * c;
        float al0 = a_attn[n], al1 = a_attn[n + 1];
        float ar0 = a_attn[OUT_DIM + n], ar1 = a_attn[OUT_DIM + n + 1];
        pl0 += d[j][0] * al0 + d[j][1] * al1;
        pr0 += d[j][0] * ar0 + d[j][1] * ar1;
        pl1 += d[j][2] * al0 + d[j][3] * al1;
        pr1 += d[j][2] * ar0 + d[j][3] * ar1;
        if (row_lo < N_NODES)
            *(float2*)(g_z + (size_t)row_lo * OUT_DIM + n) = make_float2(d[j][0], d[j][1]);
        if (row_hi < N_NODES)
            *(float2*)(g_z + (size_t)row_hi * OUT_DIM + n) = make_float2(d[j][2], d[j][3]);
    }
#pragma unroll
    for (int o = 1; o <= 2; o <<= 1) {
        pl0 += __shfl_xor_sync(0xffffffffu, pl0, o);
        pl1 += __shfl_xor_sync(0xffffffffu, pl1, o);
        pr0 += __shfl_xor_sync(0xffffffffu, pr0, o);
        pr1 += __shfl_xor_sync(0xffffffffu, pr1, o);
    }
    if (c == 0) {
        if (row_lo < N_NODES) { g_el[row_lo] = pl0; g_er[row_lo] = pr0; }
        if (row_hi < N_NODES) { g_el[row_hi] = pl1; g_er[row_hi] = pr1; }
    }
}

// ---------------- K2: histogram of dst ----------------
__global__ void k_hist(const int* __restrict__ dst) {
    int i = blockIdx.x * blockDim.x + threadIdx.x;
    if (i < N_EDGES) atomicAdd(&g_cnt[dst[i]], 1);
}

// ---------------- K3a: per-chunk exclusive scan (warp-shuffle, 2 barriers) ----------------
__global__ void __launch_bounds__(SCAN_CHUNK) k_scan1() {
    __shared__ int wsum[32];
    const int tid  = threadIdx.x;
    const int lane = tid & 31;
    const int w    = tid >> 5;
    const int i    = blockIdx.x * SCAN_CHUNK + tid;

    int x = (i < N_NODES) ? g_cnt[i] : 0;
    int v = x;
#pragma unroll
    for (int o = 1; o < 32; o <<= 1) {
        int t = __shfl_up_sync(0xffffffffu, v, o);
        if (lane >= o) v += t;
    }
    if (lane == 31) wsum[w] = v;
    __syncthreads();
    if (w == 0) {
        int y = wsum[lane];
#pragma unroll
        for (int o = 1; o < 32; o <<= 1) {
            int t = __shfl_up_sync(0xffffffffu, y, o);
            if (lane >= o) y += t;
        }
        wsum[lane] = y;   // inclusive warp sums
    }
    __syncthreads();
    int base = (w > 0) ? wsum[w - 1] : 0;
    int incl = v + base;
    if (i < N_NODES) g_off[i] = incl - x;          // exclusive within chunk
    if (tid == SCAN_CHUNK - 1) g_bsum[blockIdx.x] = incl;
}

// ---------------- K3b: scan chunk totals (single block) ----------------
__global__ void k_scan2() {
    __shared__ int sh[128];
    int tid = threadIdx.x;
    int x = (tid < NCHUNKS) ? g_bsum[tid] : 0;
    sh[tid] = x;
    __syncthreads();
#pragma unroll
    for (int off = 1; off < 128; off <<= 1) {
        int v = (tid >= off) ? sh[tid - off] : 0;
        __syncthreads();
        sh[tid] += v;
        __syncthreads();
    }
    if (tid < NCHUNKS) g_bsum[tid] = sh[tid] - x;  // exclusive
    if (tid == 0) g_off[N_NODES] = N_EDGES;
}

// ---------------- K3c: add chunk offsets, init scatter cursors ----------------
__global__ void k_scan3() {
    int i = blockIdx.x * blockDim.x + threadIdx.x;
    if (i < N_NODES) {
        int v = g_off[i] + g_bsum[i / SCAN_CHUNK];
        g_off[i] = v;
        g_pos[i] = v;
    }
}

// ---------------- K4: scatter edges into CSR ----------------
__global__ void k_scatter(const int* __restrict__ src, const int* __restrict__ dst) {
    int i = blockIdx.x * blockDim.x + threadIdx.x;
    if (i >= N_EDGES) return;
    int d = dst[i];
    int p = atomicAdd(&g_pos[d], 1);
    g_csr[p] = src[i];
}

// ---------------- K5: fused softmax + gather + ELU (HALF-warp per dst, float4) ----------------
__global__ void __launch_bounds__(256) k_aggr(float* __restrict__ out) {
    const int gid  = blockIdx.x * blockDim.x + threadIdx.x;
    const int node = gid >> 4;
    if (node >= N_NODES) return;
    const int lane = threadIdx.x & 31;
    const int l    = lane & 15;                     // lane within 16-group
    const int sub  = (lane >> 4);                   // which half-warp
    const unsigned gmask = 0xFFFFu << (16 * sub);   // group mask

    const int beg = g_off[node];
    const int end = g_off[node + 1];
    const float erd = g_er[node];

    // ---- pass A: online softmax over the group's edges ----
    const float NEG_INF = __int_as_float(0xff800000);
    float m = NEG_INF, s = 0.0f;
    for (int j = beg + l; j < end; j += 16) {
        int sn = g_csr[j];
        float e = g_el[sn] + erd;
        e = (e >= 0.0f) ? e : LEAKY * e;
        float mn = fmaxf(m, e);
        s = s * __expf(m - mn) + __expf(e - mn);
        m = mn;
    }
#pragma unroll
    for (int o = 8; o; o >>= 1) {
        float mo = __shfl_xor_sync(gmask, m, o);
        float so = __shfl_xor_sync(gmask, s, o);
        float mn = fmaxf(m, mo);
        float sa = (m  == NEG_INF) ? 0.0f : s  * __expf(m  - mn);
        float sb = (mo == NEG_INF) ? 0.0f : so * __expf(mo - mn);
        s = sa + sb;
        m = mn;
    }
    float rs = (s > 0.0f) ? (1.0f / s) : 0.0f;

    // ---- pass B: weighted float4 gather (1 LDG.128 per lane per edge) ----
    float4 acc = make_float4(0.f, 0.f, 0.f, 0.f);
    for (int j0 = beg; j0 < end; j0 += 16) {
        int j = j0 + l;
        int sn = 0;
        float ax = 0.0f;
        if (j < end) {
            sn = g_csr[j];
            float e = g_el[sn] + erd;
            e = (e >= 0.0f) ? e : LEAKY * e;
            ax = __expf(e - m) * rs;
        }
        int cnt = min(16, end - j0);
#pragma unroll 4
        for (int t = 0; t < cnt; t++) {
            int   sj = __shfl_sync(gmask, sn, 16 * sub + t);
            float aj = __shfl_sync(gmask, ax, 16 * sub + t);
            float4 v = ((const float4*)(g_z + (size_t)sj * OUT_DIM))[l];
            acc.x += aj * v.x;
            acc.y += aj * v.y;
            acc.z += aj * v.z;
            acc.w += aj * v.w;
        }
    }

    // ---- fused ELU + store (16 lanes x float4 = 64 floats) ----
    acc.x = (acc.x > 0.0f) ? acc.x : expm1f(acc.x);
    acc.y = (acc.y > 0.0f) ? acc.y : expm1f(acc.y);
    acc.z = (acc.z > 0.0f) ? acc.z : expm1f(acc.z);
    acc.w = (acc.w > 0.0f) ? acc.w : expm1f(acc.w);
    ((float4*)(out + (size_t)node * OUT_DIM))[l] = acc;
}

// ---------------- launch ----------------
extern "C" void kernel_launch(void* const* d_in, const int* in_sizes, int n_in,
                              void* d_out, int out_size) {
    const float* h      = (const float*)d_in[0];
    const float* W_fc   = (const float*)d_in[1];
    const float* a_attn = (const float*)d_in[2];
    const int*   e_src  = (const int*)d_in[3];
    const int*   e_dst  = (const int*)d_in[4];
    float* out = (float*)d_out;

    k_zero<<<(N_NODES + 255) / 256, 256>>>();
    k_gemm<<<(N_NODES + 127) / 128, 256>>>(h, W_fc, a_attn);
    k_hist<<<(N_EDGES + 255) / 256, 256>>>(e_dst);
    k_scan1<<<NCHUNKS, SCAN_CHUNK>>>();
    k_scan2<<<1, 128>>>();
    k_scan3<<<(N_NODES + 255) / 256, 256>>>();
    k_scatter<<<(N_EDGES + 255) / 256, 256>>>(e_src, e_dst);
    k_aggr<<<(N_NODES * 16 + 255) / 256, 256>>>(out);
}